// round 1
// baseline (speedup 1.0000x reference)
#include <cuda_runtime.h>
#include <cuda_bf16.h>

#define VOCAB 100000
#define EMBED 256
#define SEQ   8192

// One token per 64 threads (2 warps). Each thread handles one float4 (4 of the
// 256 embedding dims): 6 independent gathered float4 loads, sum, scale, store.
__global__ __launch_bounds__(256) void hash_ngram_kernel(
    const int*   __restrict__ tokens,
    const float* __restrict__ E3, const float* __restrict__ E4,
    const float* __restrict__ E5, const float* __restrict__ E6,
    const float* __restrict__ E7, const float* __restrict__ E8,
    float* __restrict__ out, int total)
{
    const int tid  = threadIdx.x;
    const int t    = blockIdx.x * 4 + (tid >> 6);   // token index in [0, B*S)
    if (t >= total) return;
    const int lane = tid & 63;                      // which float4 of the row
    const int i    = t & (SEQ - 1);                 // position within sequence

    // Rolling polynomial hash, incremental across n.
    // h_n(i) = (h_{n-1}(i) * 257 + b[i-(n-1)]) % VOCAB, h_1 = b[i].
    const int x = tokens[t];
    int ids[6];
    int h = x;
    #pragma unroll
    for (int n = 2; n <= 8; n++) {
        const int j  = n - 1;
        const int bj = (i >= j) ? tokens[t - j] : 0;   // zero-pad before seq start
        h = (h * 257 + bj) % VOCAB;
        if (n >= 3) ids[n - 3] = (i < n - 1) ? x : h;  // raw byte for early positions
    }

    const float* tabs[6] = {E3, E4, E5, E6, E7, E8};
    float4 acc = make_float4(0.f, 0.f, 0.f, 0.f);
    #pragma unroll
    for (int k = 0; k < 6; k++) {
        const float4* row = reinterpret_cast<const float4*>(
            tabs[k] + (size_t)ids[k] * EMBED);
        const float4 v = __ldg(&row[lane]);
        acc.x += v.x; acc.y += v.y; acc.z += v.z; acc.w += v.w;
    }
    const float inv6 = 1.0f / 6.0f;
    acc.x *= inv6; acc.y *= inv6; acc.z *= inv6; acc.w *= inv6;

    reinterpret_cast<float4*>(out)[(size_t)t * (EMBED / 4) + lane] = acc;
}

extern "C" void kernel_launch(void* const* d_in, const int* in_sizes, int n_in,
                              void* d_out, int out_size) {
    const int*   tokens = (const int*)  d_in[0];
    const float* E3     = (const float*)d_in[1];
    const float* E4     = (const float*)d_in[2];
    const float* E5     = (const float*)d_in[3];
    const float* E6     = (const float*)d_in[4];
    const float* E7     = (const float*)d_in[5];
    const float* E8     = (const float*)d_in[6];
    float* out = (float*)d_out;

    const int total  = in_sizes[0];          // B*S tokens
    const int blocks = (total + 3) / 4;      // 4 tokens per 256-thread block
    hash_ngram_kernel<<<blocks, 256>>>(tokens, E3, E4, E5, E6, E7, E8, out, total);
}

// round 3
// speedup vs baseline: 1.0082x; 1.0082x over previous
#include <cuda_runtime.h>
#include <cuda_bf16.h>

#define VOCAB 100000
#define EMBED 256
#define SEQ   8192

struct F8 { float v[8]; };

// 256-bit gather load: non-coherent, bias L2 to retain table rows (they have reuse).
// sm_103 ptxas requires v8.b32 width for the L2::evict_last modifier.
__device__ __forceinline__ F8 ldg256_evict_last(const float* p) {
    F8 r;
    asm("ld.global.nc.L2::evict_last.v8.b32 {%0,%1,%2,%3,%4,%5,%6,%7}, [%8];"
        : "=f"(r.v[0]), "=f"(r.v[1]), "=f"(r.v[2]), "=f"(r.v[3]),
          "=f"(r.v[4]), "=f"(r.v[5]), "=f"(r.v[6]), "=f"(r.v[7])
        : "l"(p));
    return r;
}

// Output store: streaming / evict-first — write-once data must not pollute L2.
__device__ __forceinline__ void stg_streaming(float* p, float a, float b, float c, float d) {
    asm volatile("st.global.cs.v4.f32 [%0], {%1,%2,%3,%4};"
                 :: "l"(p), "f"(a), "f"(b), "f"(c), "f"(d) : "memory");
}

// One token per warp. Each lane handles 8 of the 256 embedding dims:
// 6 gathered 32-byte loads, sum, scale, two streaming 16-byte stores.
__global__ __launch_bounds__(256) void hash_ngram_kernel(
    const int*   __restrict__ tokens,
    const float* __restrict__ E3, const float* __restrict__ E4,
    const float* __restrict__ E5, const float* __restrict__ E6,
    const float* __restrict__ E7, const float* __restrict__ E8,
    float* __restrict__ out, int total)
{
    const int tid  = threadIdx.x;
    const int t    = blockIdx.x * 8 + (tid >> 5);   // token index in [0, B*S)
    if (t >= total) return;
    const int lane = tid & 31;                      // which 8-float chunk of the row
    const int i    = t & (SEQ - 1);                 // position within sequence

    // Rolling polynomial hash, incremental across n.
    // h_n(i) = (h_{n-1}(i) * 257 + b[i-(n-1)]) % VOCAB, h_1 = b[i].
    const int x = tokens[t];
    int ids[6];
    int h = x;
    #pragma unroll
    for (int n = 2; n <= 8; n++) {
        const int j  = n - 1;
        const int bj = (i >= j) ? tokens[t - j] : 0;   // zero-pad before seq start
        h = (h * 257 + bj) % VOCAB;
        if (n >= 3) ids[n - 3] = (i < n - 1) ? x : h;  // raw byte for early positions
    }

    const float* tabs[6] = {E3, E4, E5, E6, E7, E8};
    float acc[8] = {0.f, 0.f, 0.f, 0.f, 0.f, 0.f, 0.f, 0.f};
    #pragma unroll
    for (int k = 0; k < 6; k++) {
        const F8 v = ldg256_evict_last(tabs[k] + (size_t)ids[k] * EMBED + lane * 8);
        #pragma unroll
        for (int e = 0; e < 8; e++) acc[e] += v.v[e];
    }
    const float inv6 = 1.0f / 6.0f;
    #pragma unroll
    for (int e = 0; e < 8; e++) acc[e] *= inv6;

    float* o = out + (size_t)t * EMBED + lane * 8;
    stg_streaming(o,     acc[0], acc[1], acc[2], acc[3]);
    stg_streaming(o + 4, acc[4], acc[5], acc[6], acc[7]);
}

extern "C" void kernel_launch(void* const* d_in, const int* in_sizes, int n_in,
                              void* d_out, int out_size) {
    const int*   tokens = (const int*)  d_in[0];
    const float* E3     = (const float*)d_in[1];
    const float* E4     = (const float*)d_in[2];
    const float* E5     = (const float*)d_in[3];
    const float* E6     = (const float*)d_in[4];
    const float* E7     = (const float*)d_in[5];
    const float* E8     = (const float*)d_in[6];
    float* out = (float*)d_out;

    const int total  = in_sizes[0];          // B*S tokens
    const int blocks = (total + 7) / 8;      // 8 tokens per 256-thread block
    hash_ngram_kernel<<<blocks, 256>>>(tokens, E3, E4, E5, E6, E7, E8, out, total);
}